// round 7
// baseline (speedup 1.0000x reference)
#include <cuda_runtime.h>

#define T_STEPS 65536
#define HID     128
#define INS     96
#define LINW    32
#define G3      384   // 3 * HID

// Scratch (allocation-free rule: __device__ globals)
__device__ float g_igates[(size_t)(T_STEPS + 1) * G3];  // +1 row pad for the t+1 prefetch
__device__ float g_hbuf[(size_t)T_STEPS * LINW];

typedef unsigned long long ull;

// ---- packed f32x2 helpers (Blackwell sm_103a) ----
__device__ __forceinline__ ull pack2(float lo, float hi) {
    ull r; asm("mov.b64 %0,{%1,%2};" : "=l"(r) : "f"(lo), "f"(hi)); return r;
}
__device__ __forceinline__ void unpack2(ull p, float& lo, float& hi) {
    asm("mov.b64 {%0,%1},%2;" : "=f"(lo), "=f"(hi) : "l"(p));
}
__device__ __forceinline__ ull ffma2(ull a, ull b, ull c) {
    ull d; asm("fma.rn.f32x2 %0,%1,%2,%3;" : "=l"(d) : "l"(a), "l"(b), "l"(c)); return d;
}
__device__ __forceinline__ ull fadd2(ull a, ull b) {
    ull d; asm("add.rn.f32x2 %0,%1,%2;" : "=l"(d) : "l"(a), "l"(b)); return d;
}

// ---- fast, overflow-safe activations (err ~1e-6, well under 1e-3 budget) ----
__device__ __forceinline__ float fsigmoid(float x) {
    float e = __expf(-x);                       // x<<0 -> e=inf -> result 0 (safe)
    return __fdividef(1.0f, 1.0f + e);
}
__device__ __forceinline__ float ftanh_f(float x) {
    float ax = fabsf(x);
    float e  = __expf(-2.0f * ax);              // in (0,1], never overflows
    float t  = __fdividef(1.0f - e, 1.0f + e);
    return copysignf(t, x);
}

// ============================================================================
// Kernel A: igates[t][j] = b_ih[j] + sum_k input_GRU[t][k] * w_ih[j][k]
// 384 threads/block (one output column each), 64 timesteps per block.
// ============================================================================
__global__ __launch_bounds__(384, 1) void igates_kernel(
    const float* __restrict__ in_gru,
    const float* __restrict__ w_ih,
    const float* __restrict__ b_ih)
{
    __shared__ __align__(16) float s_in[64 * INS];   // 24 KB input tile
    const int tid = threadIdx.x;
    const int t0  = blockIdx.x * 64;

    // cooperative tile load: 64*96 floats = 1536 float4
    {
        const float4* gsrc = (const float4*)(in_gru + (size_t)t0 * INS);
        float4* sdst = (float4*)s_in;
        for (int q = tid; q < (64 * INS) / 4; q += 384) sdst[q] = gsrc[q];
    }

    // this thread's w_ih row (96 floats) as 48 packed f32x2 in registers
    ull wq[48];
    {
        const float4* wr = (const float4*)(w_ih + (size_t)tid * INS);
        #pragma unroll
        for (int q = 0; q < 24; q++) {
            float4 v = wr[q];
            wq[2 * q]     = pack2(v.x, v.y);
            wq[2 * q + 1] = pack2(v.z, v.w);
        }
    }
    const float bias = b_ih[tid];
    __syncthreads();

    for (int tt = 0; tt < 64; tt++) {
        const ulonglong2* hp2 = (const ulonglong2*)(s_in + tt * INS);  // broadcast reads
        ull a0 = 0ull, a1 = 0ull, a2 = 0ull, a3 = 0ull;
        #pragma unroll
        for (int q = 0; q < 24; q++) {
            ulonglong2 hv = hp2[q];
            if (q & 1) { a2 = ffma2(wq[2 * q], hv.x, a2); a3 = ffma2(wq[2 * q + 1], hv.y, a3); }
            else       { a0 = ffma2(wq[2 * q], hv.x, a0); a1 = ffma2(wq[2 * q + 1], hv.y, a1); }
        }
        ull s = fadd2(fadd2(a0, a2), fadd2(a1, a3));
        float lo, hi; unpack2(s, lo, hi);
        g_igates[(size_t)(t0 + tt) * G3 + tid] = lo + hi + bias;
    }
}

// ============================================================================
// Kernel B: the sequential scan. ONE CTA, 384 threads.
// Thread j owns w_hh row j in registers (64 f32x2). Per step:
//   FMA phase (all 384): hg[j] = w_hh[j] . h          (f32x2 pipe, ~384 cyc)
//   exchange via SMEM, BAR
//   activation (threads 0..127): gates -> h_new, write h to SMEM, BAR
// igates for t+1 prefetched a full step early (DRAM latency hidden).
// h[0:32] streamed to g_hbuf (off the dependency chain).
// ============================================================================
__global__ __launch_bounds__(384, 1) void scan_kernel(
    const float* __restrict__ init_h,
    const float* __restrict__ w_hh,
    const float* __restrict__ b_n)
{
    __shared__ __align__(16) ull   hs2[HID / 2];       // h as 64 packed f32x2
    __shared__ __align__(16) float hg_s[HID * 4];      // (r,z,n,pad) per hidden unit

    const int tid = threadIdx.x;

    // weights: w_hh row tid (128 floats) -> 64 packed f32x2 in registers
    ull wq[64];
    {
        const float4* wr = (const float4*)(w_hh + (size_t)tid * HID);
        #pragma unroll
        for (int q = 0; q < 32; q++) {
            float4 v = wr[q];
            wq[2 * q]     = pack2(v.x, v.y);
            wq[2 * q + 1] = pack2(v.z, v.w);
        }
    }

    float h_old = 0.0f, bni = 0.0f;
    float irc = 0.0f, izc = 0.0f, inc = 0.0f;
    if (tid < HID) {
        h_old = init_h[tid];
        ((float*)hs2)[tid] = h_old;
        bni = b_n[tid];
        // igates for step 0
        irc = g_igates[tid];
        izc = g_igates[HID + tid];
        inc = g_igates[2 * HID + tid];
    }
    __syncthreads();

    for (int t = 0; t < T_STEPS; t++) {
        // ---- prefetch igates for step t+1 (consumed ~600 cycles from now) ----
        float irn = 0.0f, izn = 0.0f, inn = 0.0f;
        if (tid < HID) {
            const float* nx = g_igates + (size_t)(t + 1) * G3;
            irn = nx[tid]; izn = nx[HID + tid]; inn = nx[2 * HID + tid];
        }

        // ---- FMA phase: hg = w_hh[tid] . h (broadcast LDS.128 + FFMA2) ----
        {
            const ulonglong2* hp2 = (const ulonglong2*)hs2;
            ull a0 = 0ull, a1 = 0ull, a2 = 0ull, a3 = 0ull;
            #pragma unroll
            for (int q = 0; q < 32; q++) {
                ulonglong2 hv = hp2[q];
                if (q & 1) { a2 = ffma2(wq[2 * q], hv.x, a2); a3 = ffma2(wq[2 * q + 1], hv.y, a3); }
                else       { a0 = ffma2(wq[2 * q], hv.x, a0); a1 = ffma2(wq[2 * q + 1], hv.y, a1); }
            }
            ull s = fadd2(fadd2(a0, a2), fadd2(a1, a3));
            float lo, hi; unpack2(s, lo, hi);
            // interleave gates: unit i gets (r,z,n) contiguous -> one LDS.128 read
            hg_s[(tid & (HID - 1)) * 4 + (tid >> 7)] = lo + hi;
        }
        __syncthreads();   // hg ready; also: everyone done reading hs2

        // ---- activation (warps 0..3 only; warp-uniform branch) ----
        if (tid < HID) {
            float4 g = *(const float4*)&hg_s[tid * 4];      // (hr, hz, hn, -)
            float r = fsigmoid(irc + g.x);
            float z = fsigmoid(izc + g.y);
            float y = inc + r * (g.z + bni);
            float n = ftanh_f(y);
            float hnew = n + z * (h_old - n);               // equinox GRUCell
            h_old = hnew;
            ((float*)hs2)[tid] = hnew;
            if (tid < LINW) g_hbuf[(size_t)t * LINW + tid] = hnew;  // off critical path
            irc = irn; izc = izn; inc = inn;
        }
        __syncthreads();   // h ready for next step's FMA phase
    }
}

// ============================================================================
// Kernel C: out[t] = dot(h[t][:32], x_lin[t]) + lin_bias
// ============================================================================
__global__ void out_kernel(
    const float* __restrict__ x_lin,
    const float* __restrict__ lin_bias,
    float* __restrict__ out)
{
    int t = blockIdx.x * blockDim.x + threadIdx.x;
    if (t >= T_STEPS) return;
    const float4* h4 = (const float4*)(g_hbuf + (size_t)t * LINW);
    const float4* x4 = (const float4*)(x_lin + (size_t)t * LINW);
    float acc = 0.0f;
    #pragma unroll
    for (int q = 0; q < 8; q++) {
        float4 a = h4[q], b = x4[q];
        acc += a.x * b.x + a.y * b.y + a.z * b.z + a.w * b.w;
    }
    out[t] = acc + lin_bias[0];
}

// ============================================================================
extern "C" void kernel_launch(void* const* d_in, const int* in_sizes, int n_in,
                              void* d_out, int out_size)
{
    const float* in_gru   = (const float*)d_in[0];  // (T, 96)
    const float* in_lin   = (const float*)d_in[1];  // (T, 32)
    const float* init_h   = (const float*)d_in[2];  // (128,)
    const float* w_ih     = (const float*)d_in[3];  // (384, 96)
    const float* w_hh     = (const float*)d_in[4];  // (384, 128)
    const float* b_ih     = (const float*)d_in[5];  // (384,)
    const float* b_n      = (const float*)d_in[6];  // (128,)
    const float* lin_bias = (const float*)d_in[7];  // (1,)

    igates_kernel<<<T_STEPS / 64, 384>>>(in_gru, w_ih, b_ih);
    scan_kernel<<<1, 384>>>(init_h, w_hh, b_n);
    out_kernel<<<T_STEPS / 256, 256>>>(in_lin, lin_bias, (float*)d_out);
}